// round 1
// baseline (speedup 1.0000x reference)
#include <cuda_runtime.h>
#include <math.h>

#define TT 4096
#define DD 256
#define HH 1024
#define EE 8

// ---------------- device-global scratch (allocation-free) ----------------
__device__ int   g_count[EE];
__device__ int   g_tok[EE * TT];            // token id per (expert,row)
__device__ int   g_pos[TT * 2];             // token,slot -> e*TT+p row index
__device__ float g_gv[TT * 2];              // gate values per slot
__device__ float g_h1[(size_t)EE * TT * HH];  // 128 MB intermediate
__device__ float g_o2[(size_t)EE * TT * DD];  // 32 MB expert outputs

// ---------------- helpers ----------------
__device__ __forceinline__ unsigned f2tf(float f) {
    unsigned r;
    asm("cvt.rna.tf32.f32 %0, %1;" : "=r"(r) : "f"(f));
    return r;
}

__device__ __forceinline__ void mma8(float* c, const unsigned* a, const unsigned* b) {
    asm volatile(
        "mma.sync.aligned.m16n8k8.row.col.f32.tf32.tf32.f32 "
        "{%0,%1,%2,%3}, {%4,%5,%6,%7}, {%8,%9}, {%0,%1,%2,%3};\n"
        : "+f"(c[0]), "+f"(c[1]), "+f"(c[2]), "+f"(c[3])
        : "r"(a[0]), "r"(a[1]), "r"(a[2]), "r"(a[3]), "r"(b[0]), "r"(b[1]));
}

// ---------------- kernel 0: zero counters ----------------
__global__ void zero_counts_kernel() {
    if (threadIdx.x < EE) g_count[threadIdx.x] = 0;
}

// ---------------- kernel 1: gating (one warp per token) ----------------
__global__ void gate_kernel(const float* __restrict__ x, const float* __restrict__ wg) {
    __shared__ float swg[DD * EE];  // 8 KB
    const int tid = threadIdx.x;
    for (int i = tid; i < DD * EE; i += 128) swg[i] = wg[i];
    __syncthreads();
    const int lane = tid & 31, warp = tid >> 5;
    const int t = blockIdx.x * 4 + warp;

    float xr[8];
#pragma unroll
    for (int j = 0; j < 8; j++) xr[j] = x[(size_t)t * DD + lane + 32 * j];

    float logit[EE];
#pragma unroll
    for (int e = 0; e < EE; e++) {
        float p = 0.f;
#pragma unroll
        for (int j = 0; j < 8; j++) p += xr[j] * swg[(lane + 32 * j) * EE + e];
#pragma unroll
        for (int off = 16; off > 0; off >>= 1) p += __shfl_xor_sync(0xffffffffu, p, off);
        logit[e] = p;
    }

    if (lane == 0) {
        int i0 = 0; float v0 = logit[0];
#pragma unroll
        for (int e = 1; e < EE; e++) if (logit[e] > v0) { v0 = logit[e]; i0 = e; }
        int i1 = -1; float v1 = -INFINITY;
#pragma unroll
        for (int e = 0; e < EE; e++) if (e != i0 && logit[e] > v1) { v1 = logit[e]; i1 = e; }

        const float e1  = expf(v1 - v0);          // v0 >= v1, stable
        const float inv = 1.f / (1.f + e1);
        const float g0 = inv, g1 = e1 * inv;

        int p0 = atomicAdd(&g_count[i0], 1);
        g_tok[i0 * TT + p0] = t;
        g_pos[t * 2 + 0]    = i0 * TT + p0;
        g_gv[t * 2 + 0]     = g0;

        int p1 = atomicAdd(&g_count[i1], 1);
        g_tok[i1 * TT + p1] = t;
        g_pos[t * 2 + 1]    = i1 * TT + p1;
        g_gv[t * 2 + 1]     = g1;
    }
}

// ---------------- grouped TF32 GEMM: 64x128 tile, BK=16, 8 warps ----------------
// GATHER=true : A = x rows gathered by g_tok, C = g_h1, epilogue ReLU(.+b1)
// GATHER=false: A = g_h1 rows,                C = g_o2, epilogue (.+b2)
template <int NDIM, int KDIM, bool GATHER, bool RELU>
__global__ void __launch_bounds__(256) moe_gemm_kernel(
    const float* __restrict__ Abase, const float* __restrict__ Bbase,
    const float* __restrict__ bias)
{
    constexpr int BK = 16;
    constexpr int NK = KDIM / BK;
    __shared__ unsigned sa[2][BK][72];    // [k][m], stride 72  (8 mod 32 -> conflict-free frags)
    __shared__ unsigned sb[2][BK][136];   // [k][n], stride 136 (8 mod 32)

    const int e = blockIdx.z;
    const int M = g_count[e];
    const int row0 = blockIdx.y * 64;
    if (row0 >= M) return;
    const int col0 = blockIdx.x * 128;

    const int tid = threadIdx.x;
    const int lane = tid & 31, warp = tid >> 5;
    const int wm = warp >> 2, wn = warp & 3;       // 2 x 4 warp grid
    const int grp = lane >> 2, tg = lane & 3;

    // A copy mapping: 4 threads per row, float4 each (64 rows x 16 k)
    const int ar  = tid >> 2;
    const int ak4 = (tid & 3) * 4;
    const bool avalid = (row0 + ar) < M;
    const float* Arow;
    if (GATHER) {
        const int tok = avalid ? g_tok[e * TT + row0 + ar] : 0;
        Arow = Abase + (size_t)tok * KDIM;
    } else {
        Arow = g_h1 + ((size_t)e * TT + row0 + ar) * KDIM;
    }

    // B copy mapping: warp = k-row (and k+8), lane = float4 column
    const float* Bexp = Bbase + (size_t)e * KDIM * NDIM;
    const int bk = warp;
    const int bc = lane * 4;

    float acc[2][4][4];
#pragma unroll
    for (int i = 0; i < 2; i++)
#pragma unroll
        for (int j = 0; j < 4; j++)
#pragma unroll
            for (int q = 0; q < 4; q++) acc[i][j][q] = 0.f;

    float4 aR, b0R, b1R;
    // prologue: stage 0
    aR  = avalid ? *(const float4*)(Arow + ak4) : make_float4(0.f, 0.f, 0.f, 0.f);
    b0R = *(const float4*)(Bexp + (size_t)bk * NDIM + col0 + bc);
    b1R = *(const float4*)(Bexp + (size_t)(bk + 8) * NDIM + col0 + bc);
    sa[0][ak4 + 0][ar] = f2tf(aR.x);
    sa[0][ak4 + 1][ar] = f2tf(aR.y);
    sa[0][ak4 + 2][ar] = f2tf(aR.z);
    sa[0][ak4 + 3][ar] = f2tf(aR.w);
    {
        uint4 u0 = { f2tf(b0R.x), f2tf(b0R.y), f2tf(b0R.z), f2tf(b0R.w) };
        uint4 u1 = { f2tf(b1R.x), f2tf(b1R.y), f2tf(b1R.z), f2tf(b1R.w) };
        *(uint4*)&sb[0][bk][bc]     = u0;
        *(uint4*)&sb[0][bk + 8][bc] = u1;
    }
    __syncthreads();

#pragma unroll 1
    for (int kt = 0; kt < NK; kt++) {
        const int cur = kt & 1;
        if (kt + 1 < NK) {
            const int ko = (kt + 1) * BK;
            aR  = avalid ? *(const float4*)(Arow + ko + ak4) : make_float4(0.f, 0.f, 0.f, 0.f);
            b0R = *(const float4*)(Bexp + (size_t)(ko + bk) * NDIM + col0 + bc);
            b1R = *(const float4*)(Bexp + (size_t)(ko + bk + 8) * NDIM + col0 + bc);
        }
#pragma unroll
        for (int k8 = 0; k8 < BK; k8 += 8) {
            unsigned af[2][4], bf[4][2];
#pragma unroll
            for (int mt = 0; mt < 2; mt++) {
                const int r = wm * 32 + mt * 16 + grp;
                af[mt][0] = sa[cur][k8 + tg][r];
                af[mt][1] = sa[cur][k8 + tg][r + 8];
                af[mt][2] = sa[cur][k8 + tg + 4][r];
                af[mt][3] = sa[cur][k8 + tg + 4][r + 8];
            }
#pragma unroll
            for (int nt = 0; nt < 4; nt++) {
                const int c = wn * 32 + nt * 8 + grp;
                bf[nt][0] = sb[cur][k8 + tg][c];
                bf[nt][1] = sb[cur][k8 + tg + 4][c];
            }
#pragma unroll
            for (int mt = 0; mt < 2; mt++)
#pragma unroll
                for (int nt = 0; nt < 4; nt++)
                    mma8(acc[mt][nt], af[mt], bf[nt]);
        }
        if (kt + 1 < NK) {
            const int nxt = cur ^ 1;
            sa[nxt][ak4 + 0][ar] = f2tf(aR.x);
            sa[nxt][ak4 + 1][ar] = f2tf(aR.y);
            sa[nxt][ak4 + 2][ar] = f2tf(aR.z);
            sa[nxt][ak4 + 3][ar] = f2tf(aR.w);
            uint4 u0 = { f2tf(b0R.x), f2tf(b0R.y), f2tf(b0R.z), f2tf(b0R.w) };
            uint4 u1 = { f2tf(b1R.x), f2tf(b1R.y), f2tf(b1R.z), f2tf(b1R.w) };
            *(uint4*)&sb[nxt][bk][bc]     = u0;
            *(uint4*)&sb[nxt][bk + 8][bc] = u1;
            __syncthreads();
        }
    }

    // epilogue: bias (+ReLU), guarded float2 stores
    const float* bv = bias + e * NDIM;
    float* Cb;
    if (RELU) Cb = g_h1; else Cb = g_o2;
#pragma unroll
    for (int mt = 0; mt < 2; mt++) {
        const int lr = wm * 32 + mt * 16 + grp;
#pragma unroll
        for (int half = 0; half < 2; half++) {
            const int r = row0 + lr + half * 8;
            if (r < M) {
                float* crow = Cb + ((size_t)e * TT + r) * NDIM;
#pragma unroll
                for (int nt = 0; nt < 4; nt++) {
                    const int c = col0 + wn * 32 + nt * 8 + 2 * tg;
                    float v0 = acc[mt][nt][half * 2 + 0] + bv[c];
                    float v1 = acc[mt][nt][half * 2 + 1] + bv[c + 1];
                    if (RELU) { v0 = fmaxf(v0, 0.f); v1 = fmaxf(v1, 0.f); }
                    *(float2*)(crow + c) = make_float2(v0, v1);
                }
            }
        }
    }
}

// ---------------- kernel 4: gated combine (deterministic, no atomics) ----------------
__global__ void combine_kernel(float* __restrict__ y) {
    const int t  = blockIdx.x;
    const int d4 = threadIdx.x;  // 0..63 (float4 lanes over D=256)
    const int   p0 = g_pos[t * 2],     p1 = g_pos[t * 2 + 1];
    const float g0 = g_gv[t * 2],      g1 = g_gv[t * 2 + 1];
    const float4 a = *(const float4*)(g_o2 + (size_t)p0 * DD + d4 * 4);
    const float4 b = *(const float4*)(g_o2 + (size_t)p1 * DD + d4 * 4);
    float4 r;
    r.x = g0 * a.x + g1 * b.x;
    r.y = g0 * a.y + g1 * b.y;
    r.z = g0 * a.z + g1 * b.z;
    r.w = g0 * a.w + g1 * b.w;
    *(float4*)(y + (size_t)t * DD + d4 * 4) = r;
}

// ---------------- launch ----------------
extern "C" void kernel_launch(void* const* d_in, const int* in_sizes, int n_in,
                              void* d_out, int out_size) {
    const float* x  = (const float*)d_in[0];   // h       (B,N,D)
    const float* wg = (const float*)d_in[1];   // w_gate  (D,E)
    const float* W1 = (const float*)d_in[2];   // (E,D,H)
    const float* b1 = (const float*)d_in[3];   // (E,H)
    const float* W2 = (const float*)d_in[4];   // (E,H,D)
    const float* b2 = (const float*)d_in[5];   // (E,D)
    float* y = (float*)d_out;                  // (B,N,D) fp32

    zero_counts_kernel<<<1, 32>>>();
    gate_kernel<<<TT / 4, 128>>>(x, wg);
    moe_gemm_kernel<HH, DD, true,  true ><<<dim3(HH / 128, TT / 64, EE), 256>>>(x, W1, b1);
    moe_gemm_kernel<DD, HH, false, false><<<dim3(DD / 128, TT / 64, EE), 256>>>(nullptr, W2, b2);
    combine_kernel<<<TT, 64>>>(y);
}